// round 6
// baseline (speedup 1.0000x reference)
#include <cuda_runtime.h>
#include <cuda_bf16.h>
#include <cstdint>

#define BN_T 2048
#define DM   1024
#define NH   16
#define HD   64
#define MROWS 8192   // B*T

// ---------------------------------------------------------------------------
// Device-global scratch (allocation-free per harness rules)
// ---------------------------------------------------------------------------
__device__ __align__(16) __nv_bfloat16 g_xh[MROWS * DM];
__device__ __align__(16) __nv_bfloat16 g_xl[MROWS * DM];
__device__ __align__(16) __nv_bfloat16 g_wqkvh[3 * DM * DM];
__device__ __align__(16) __nv_bfloat16 g_wqkvl[3 * DM * DM];
__device__ __align__(16) __nv_bfloat16 g_woh[DM * DM];
__device__ __align__(16) __nv_bfloat16 g_wol[DM * DM];
__device__ __align__(16) __nv_bfloat16 g_qkvh[MROWS * 3 * DM];
__device__ __align__(16) __nv_bfloat16 g_qkvl[MROWS * 3 * DM];
__device__ __align__(16) __nv_bfloat16 g_yh[MROWS * DM];
__device__ __align__(16) __nv_bfloat16 g_yl[MROWS * DM];

// ---------------------------------------------------------------------------
// PTX helpers (baseline PTX only: cp.async + ldmatrix + mma.sync)
// ---------------------------------------------------------------------------
__device__ __forceinline__ uint32_t smem_u32(const void* p) {
    uint32_t a;
    asm("{ .reg .u64 t; cvta.to.shared.u64 t, %1; cvt.u32.u64 %0, t; }"
        : "=r"(a) : "l"(p));
    return a;
}

__device__ __forceinline__ void cp_async16(uint32_t saddr, const void* gaddr) {
    asm volatile("cp.async.cg.shared.global [%0], [%1], 16;"
                 :: "r"(saddr), "l"(gaddr) : "memory");
}
#define CP_COMMIT() asm volatile("cp.async.commit_group;" ::: "memory")
#define CP_WAIT(n)  asm volatile("cp.async.wait_group %0;" :: "n"(n) : "memory")

__device__ __forceinline__ void ldm4(uint32_t* r, uint32_t addr) {
    asm volatile("ldmatrix.sync.aligned.m8n8.x4.shared.b16 {%0,%1,%2,%3}, [%4];"
                 : "=r"(r[0]), "=r"(r[1]), "=r"(r[2]), "=r"(r[3]) : "r"(addr));
}
__device__ __forceinline__ void ldm4t(uint32_t* r, uint32_t addr) {
    asm volatile("ldmatrix.sync.aligned.m8n8.x4.trans.shared.b16 {%0,%1,%2,%3}, [%4];"
                 : "=r"(r[0]), "=r"(r[1]), "=r"(r[2]), "=r"(r[3]) : "r"(addr));
}

__device__ __forceinline__ void mma_bf16(float* d, const uint32_t* a,
                                         uint32_t b0, uint32_t b1) {
    asm volatile(
        "mma.sync.aligned.m16n8k16.row.col.f32.bf16.bf16.f32 "
        "{%0,%1,%2,%3}, {%4,%5,%6,%7}, {%8,%9}, {%0,%1,%2,%3};"
        : "+f"(d[0]), "+f"(d[1]), "+f"(d[2]), "+f"(d[3])
        : "r"(a[0]), "r"(a[1]), "r"(a[2]), "r"(a[3]), "r"(b0), "r"(b1));
}

// ---------------------------------------------------------------------------
// fp32 -> (hi, lo) bf16 split, 4 elems/thread
// ---------------------------------------------------------------------------
__global__ __launch_bounds__(256) void split_bf16(
    const float* __restrict__ in,
    __nv_bfloat16* __restrict__ hi,
    __nv_bfloat16* __restrict__ lo,
    int n4)
{
    int i = blockIdx.x * blockDim.x + threadIdx.x;
    if (i >= n4) return;
    float4 v = ((const float4*)in)[i];
    __nv_bfloat16 h0 = __float2bfloat16(v.x);
    __nv_bfloat16 h1 = __float2bfloat16(v.y);
    __nv_bfloat16 h2 = __float2bfloat16(v.z);
    __nv_bfloat16 h3 = __float2bfloat16(v.w);
    __nv_bfloat16 l0 = __float2bfloat16(v.x - __bfloat162float(h0));
    __nv_bfloat16 l1 = __float2bfloat16(v.y - __bfloat162float(h1));
    __nv_bfloat16 l2 = __float2bfloat16(v.z - __bfloat162float(h2));
    __nv_bfloat16 l3 = __float2bfloat16(v.w - __bfloat162float(h3));
    __nv_bfloat162 hp0(h0, h1), hp1(h2, h3), lp0(l0, l1), lp1(l2, l3);
    ((__nv_bfloat162*)hi)[i * 2]     = hp0;
    ((__nv_bfloat162*)hi)[i * 2 + 1] = hp1;
    ((__nv_bfloat162*)lo)[i * 2]     = lp0;
    ((__nv_bfloat162*)lo)[i * 2 + 1] = lp1;
}

// ---------------------------------------------------------------------------
// C = A @ B^T + bias, split bf16 3-pass HMMA.
// OUTM=0: fp32 C.  OUTM=1: split bf16 (Ch, Cl).
// Pass-major MMA order: same-accumulator MMAs separated by 15 independent.
// ---------------------------------------------------------------------------
#define STAGE_BYTES 32768
#define GEMM_SMEM  (3 * STAGE_BYTES)

__device__ __forceinline__ uint32_t sw_off(int row, int c) {
    return (uint32_t)(row * 64 + ((c ^ ((row >> 1) & 3)) * 16));
}

template<int OUTM>
__global__ __launch_bounds__(256, 1) void gemm_bf16x3(
    const __nv_bfloat16* __restrict__ Ah, const __nv_bfloat16* __restrict__ Al,
    const __nv_bfloat16* __restrict__ Bh, const __nv_bfloat16* __restrict__ Bl,
    const float* __restrict__ bias,
    float* __restrict__ C,
    __nv_bfloat16* __restrict__ Ch, __nv_bfloat16* __restrict__ Cl,
    int N, int K)
{
    extern __shared__ char smem[];
    const uint32_t sb = smem_u32(smem);
    const int tid = threadIdx.x;
    const int lane = tid & 31;
    const int wid = tid >> 5;
    const int warpM = wid & 3;
    const int warpN = wid >> 2;
    const int bm = blockIdx.y * 128;
    const int bn = blockIdx.x * 128;
    const int NC = K >> 5;

    const int g  = lane >> 3;
    const int l7 = lane & 7;
    const int arow = (g & 1) * 8 + l7;
    const int acg  = g >> 1;
    const int brow = (g >> 1) * 8 + l7;
    const int bcg  = g & 1;

    uint32_t aRow[2], aSw[2];
#pragma unroll
    for (int mt = 0; mt < 2; mt++) {
        int r = warpM * 32 + mt * 16 + arow;
        aRow[mt] = (uint32_t)(r * 64);
        aSw[mt] = (uint32_t)((r >> 1) & 3);
    }
    uint32_t bRow[4], bSw[4];
#pragma unroll
    for (int ng = 0; ng < 4; ng++) {
        int r = warpN * 64 + ng * 16 + brow;
        bRow[ng] = (uint32_t)(r * 64);
        bSw[ng] = (uint32_t)((r >> 1) & 3);
    }

    float acc[2][8][4];
#pragma unroll
    for (int mt = 0; mt < 2; mt++)
#pragma unroll
        for (int nt = 0; nt < 8; nt++)
#pragma unroll
            for (int e = 0; e < 4; e++) acc[mt][nt][e] = 0.f;

    const __nv_bfloat16* srcA[2] = { Ah + (size_t)bm * K, Al + (size_t)bm * K };
    const __nv_bfloat16* srcB[2] = { Bh + (size_t)bn * K, Bl + (size_t)bn * K };

    auto load_stage = [&](int kc, int st) {
        const uint32_t stbase = sb + st * STAGE_BYTES;
#pragma unroll
        for (int q = 0; q < 8; q++) {
            int cid = tid + q * 256;
            int sub = cid >> 9;
            int ci  = cid & 511;
            int row = ci >> 2;
            int c   = ci & 3;
            uint32_t saddr = stbase + sub * 8192 + sw_off(row, c);
            const __nv_bfloat16* gp =
                (sub < 2 ? srcA[sub] : srcB[sub - 2])
                + (size_t)row * K + kc * 32 + c * 8;
            cp_async16(saddr, gp);
        }
        CP_COMMIT();
    };

    load_stage(0, 0);
    load_stage(1, 1);

    for (int i = 0; i < NC; i++) {
        if (i < NC - 1) { CP_WAIT(1); } else { CP_WAIT(0); }
        __syncthreads();

        const uint32_t stbase = sb + (i % 3) * STAGE_BYTES;
#pragma unroll
        for (int ks = 0; ks < 2; ks++) {
            uint32_t ah[2][4], al[2][4];
#pragma unroll
            for (int mt = 0; mt < 2; mt++) {
                uint32_t slot = (uint32_t)((2 * ks + acg) ^ aSw[mt]) * 16;
                ldm4(ah[mt], stbase + 0    + aRow[mt] + slot);
                ldm4(al[mt], stbase + 8192 + aRow[mt] + slot);
            }
            uint32_t bh[4][4], bl[4][4];
#pragma unroll
            for (int ng = 0; ng < 4; ng++) {
                uint32_t slot = (uint32_t)((2 * ks + bcg) ^ bSw[ng]) * 16;
                ldm4(bh[ng], stbase + 16384 + bRow[ng] + slot);
                ldm4(bl[ng], stbase + 24576 + bRow[ng] + slot);
            }
            // pass 1: Ah * Bh  (16 independent MMAs)
#pragma unroll
            for (int mt = 0; mt < 2; mt++)
#pragma unroll
                for (int ng = 0; ng < 4; ng++) {
                    mma_bf16(acc[mt][2 * ng],     ah[mt], bh[ng][0], bh[ng][1]);
                    mma_bf16(acc[mt][2 * ng + 1], ah[mt], bh[ng][2], bh[ng][3]);
                }
            // pass 2: Ah * Bl
#pragma unroll
            for (int mt = 0; mt < 2; mt++)
#pragma unroll
                for (int ng = 0; ng < 4; ng++) {
                    mma_bf16(acc[mt][2 * ng],     ah[mt], bl[ng][0], bl[ng][1]);
                    mma_bf16(acc[mt][2 * ng + 1], ah[mt], bl[ng][2], bl[ng][3]);
                }
            // pass 3: Al * Bh
#pragma unroll
            for (int mt = 0; mt < 2; mt++)
#pragma unroll
                for (int ng = 0; ng < 4; ng++) {
                    mma_bf16(acc[mt][2 * ng],     al[mt], bh[ng][0], bh[ng][1]);
                    mma_bf16(acc[mt][2 * ng + 1], al[mt], bh[ng][2], bh[ng][3]);
                }
        }

        __syncthreads();
        if (i + 2 < NC) load_stage(i + 2, (i + 2) % 3);
    }

#pragma unroll
    for (int mt = 0; mt < 2; mt++) {
#pragma unroll
        for (int nt = 0; nt < 8; nt++) {
            int row0 = bm + warpM * 32 + mt * 16 + (lane >> 2);
            int col  = bn + warpN * 64 + nt * 8 + (lane & 3) * 2;
            float b0 = bias[col], b1 = bias[col + 1];
            float v0 = acc[mt][nt][0] + b0, v1 = acc[mt][nt][1] + b1;
            float v2 = acc[mt][nt][2] + b0, v3 = acc[mt][nt][3] + b1;
            if (OUTM == 0) {
                float2 p0 = { v0, v1 }, p1 = { v2, v3 };
                *(float2*)(C + (size_t)row0 * N + col) = p0;
                *(float2*)(C + (size_t)(row0 + 8) * N + col) = p1;
            } else {
                __nv_bfloat16 h0 = __float2bfloat16(v0), h1 = __float2bfloat16(v1);
                __nv_bfloat16 h2 = __float2bfloat16(v2), h3 = __float2bfloat16(v3);
                __nv_bfloat162 hp0(h0, h1), hp1(h2, h3);
                __nv_bfloat162 lp0(__float2bfloat16(v0 - __bfloat162float(h0)),
                                   __float2bfloat16(v1 - __bfloat162float(h1)));
                __nv_bfloat162 lp1(__float2bfloat16(v2 - __bfloat162float(h2)),
                                   __float2bfloat16(v3 - __bfloat162float(h3)));
                *(uint32_t*)(Ch + (size_t)row0 * N + col) = *(uint32_t*)&hp0;
                *(uint32_t*)(Cl + (size_t)row0 * N + col) = *(uint32_t*)&lp0;
                *(uint32_t*)(Ch + (size_t)(row0 + 8) * N + col) = *(uint32_t*)&hp1;
                *(uint32_t*)(Cl + (size_t)(row0 + 8) * N + col) = *(uint32_t*)&lp1;
            }
        }
    }
}

// ---------------------------------------------------------------------------
// Causal flash attention, bf16x3 HMMA; pass-major MMA ordering.
// grid (16, B*NH); CTA: 128-query tile for one (b,h); 256 threads / 8 warps.
// ---------------------------------------------------------------------------
#define FSMEM (32768 + 2 * 32768)   // Qh|Ql (32K) + 2 stages of Kh|Kl|Vh|Vl

__global__ __launch_bounds__(256, 1) void flash_hmma(
    const __nv_bfloat16* __restrict__ qkvh,
    const __nv_bfloat16* __restrict__ qkvl,
    const int* __restrict__ mask,
    __nv_bfloat16* __restrict__ yh,
    __nv_bfloat16* __restrict__ yl)
{
    extern __shared__ char smem[];
    const uint32_t sb = smem_u32(smem);
    const int tid = threadIdx.x;
    const int lane = tid & 31, wid = tid >> 5;
    const int qt = 15 - (int)blockIdx.x;          // descending work order
    const int bh = blockIdx.y, b = bh >> 4, h = bh & 15;
    const int nkt = 2 * qt + 2;
    const int l7 = lane & 7, bit3 = (lane >> 3) & 1, bit4 = (lane >> 4) & 1;

    const uint32_t QH = sb, QL = sb + 16384, ST = sb + 32768;

    // Q load: 128 rows x 128B x {h,l}
    {
        const size_t rq = (size_t)(b * BN_T + qt * 128);
#pragma unroll
        for (int q = 0; q < 8; q++) {
            int cid = q * 256 + tid;
            int arr = cid >> 10, ci = cid & 1023, row = ci >> 3, c = ci & 7;
            const __nv_bfloat16* gp = (arr ? qkvl : qkvh)
                + (rq + row) * 3072 + h * 64 + c * 8;
            cp_async16(sb + arr * 16384 + row * 128 + (((c ^ (row & 7))) << 4), gp);
        }
        CP_COMMIT();
    }

    auto load_kv = [&](int kt, int st) {
        const uint32_t base = ST + st * 32768;
        const size_t rk = (size_t)(b * BN_T + kt * 64);
#pragma unroll
        for (int q = 0; q < 8; q++) {
            int cid = q * 256 + tid;
            int sub = cid >> 9, ci = cid & 511, row = ci >> 3, c = ci & 7;
            const __nv_bfloat16* src = (sub & 1) ? qkvl : qkvh;
            int colb = (sub >> 1) ? (2048 + h * 64) : (1024 + h * 64);
            const __nv_bfloat16* gp = src + (rk + row) * 3072 + colb + c * 8;
            cp_async16(base + sub * 8192 + row * 128 + (((c ^ (row & 7))) << 4), gp);
        }
        CP_COMMIT();
    };

    load_kv(0, 0);
    load_kv(1, 1);

    CP_WAIT(2);            // Q resident
    __syncthreads();

    // Q fragments (register-resident)
    uint32_t qhf[4][4], qlf[4][4];
    {
        const uint32_t rb = (uint32_t)((wid * 16 + bit3 * 8 + l7) * 128);
#pragma unroll
        for (int ks = 0; ks < 4; ks++) {
            uint32_t sl = ((uint32_t)((ks * 2 + bit4) ^ l7)) << 4;
            ldm4(qhf[ks], QH + rb + sl);
            ldm4(qlf[ks], QL + rb + sl);
        }
    }

    float o[8][4];
#pragma unroll
    for (int nt = 0; nt < 8; nt++)
#pragma unroll
        for (int e = 0; e < 4; e++) o[nt][e] = 0.f;
    float m0 = -1e30f, m1 = -1e30f, l0 = 0.f, l1 = 0.f;

    const int row0 = qt * 128 + wid * 16 + (lane >> 2);
    const int col_in = (lane & 3) * 2;

    for (int kt = 0; kt < nkt; kt++) {
        if (kt + 1 < nkt) { CP_WAIT(1); } else { CP_WAIT(0); }
        __syncthreads();
        const uint32_t kb = ST + (kt & 1) * 32768;

        // ---- S = (Q Kᵀ) * 0.125, 3-pass ----
        float s[8][4];
#pragma unroll
        for (int nt = 0; nt < 8; nt++)
#pragma unroll
            for (int e = 0; e < 4; e++) s[nt][e] = 0.f;

#pragma unroll
        for (int ks = 0; ks < 4; ks++) {
            uint32_t kh4[4][4], kl4[4][4];
#pragma unroll
            for (int np = 0; np < 4; np++) {
                uint32_t rb = (uint32_t)((np * 16 + bit4 * 8 + l7) * 128);
                uint32_t sl = ((uint32_t)((ks * 2 + bit3) ^ l7)) << 4;
                ldm4(kh4[np], kb + rb + sl);
                ldm4(kl4[np], kb + 8192 + rb + sl);
            }
            // pass 1: Qh * Kh  (8 independent)
#pragma unroll
            for (int np = 0; np < 4; np++) {
                mma_bf16(s[2*np],   qhf[ks], kh4[np][0], kh4[np][1]);
                mma_bf16(s[2*np+1], qhf[ks], kh4[np][2], kh4[np][3]);
            }
            // pass 2: Qh * Kl
#pragma unroll
            for (int np = 0; np < 4; np++) {
                mma_bf16(s[2*np],   qhf[ks], kl4[np][0], kl4[np][1]);
                mma_bf16(s[2*np+1], qhf[ks], kl4[np][2], kl4[np][3]);
            }
            // pass 3: Ql * Kh
#pragma unroll
            for (int np = 0; np < 4; np++) {
                mma_bf16(s[2*np],   qlf[ks], kh4[np][0], kh4[np][1]);
                mma_bf16(s[2*np+1], qlf[ks], kh4[np][2], kh4[np][3]);
            }
        }

        const bool diag = (kt >= 2 * qt);
#pragma unroll
        for (int nt = 0; nt < 8; nt++) {
#pragma unroll
            for (int e = 0; e < 4; e++) s[nt][e] *= 0.125f;
            if (diag) {
                int key = kt * 64 + nt * 8 + col_in;
                if (key     > row0)     s[nt][0] = -1e30f;
                if (key + 1 > row0)     s[nt][1] = -1e30f;
                if (key     > row0 + 8) s[nt][2] = -1e30f;
                if (key + 1 > row0 + 8) s[nt][3] = -1e30f;
            }
        }

        // ---- online softmax ----
        float rm0 = s[0][0], rm1 = s[0][2];
#pragma unroll
        for (int nt = 0; nt < 8; nt++) {
            rm0 = fmaxf(rm0, fmaxf(s[nt][0], s[nt][1]));
            rm1 = fmaxf(rm1, fmaxf(s[nt][2], s[nt][3]));
        }
        rm0 = fmaxf(rm0, __shfl_xor_sync(~0u, rm0, 1));
        rm0 = fmaxf(rm0, __shfl_xor_sync(~0u, rm0, 2));
        rm1 = fmaxf(rm1, __shfl_xor_sync(~0u, rm1, 1));
        rm1 = fmaxf(rm1, __shfl_xor_sync(~0u, rm1, 2));
        float mn0 = fmaxf(m0, rm0), mn1 = fmaxf(m1, rm1);
        float c0 = __expf(m0 - mn0), c1 = __expf(m1 - mn1);
        float sum0 = 0.f, sum1 = 0.f;
#pragma unroll
        for (int nt = 0; nt < 8; nt++) {
            s[nt][0] = __expf(s[nt][0] - mn0);
            s[nt][1] = __expf(s[nt][1] - mn0);
            s[nt][2] = __expf(s[nt][2] - mn1);
            s[nt][3] = __expf(s[nt][3] - mn1);
            sum0 += s[nt][0] + s[nt][1];
            sum1 += s[nt][2] + s[nt][3];
        }
        sum0 += __shfl_xor_sync(~0u, sum0, 1);
        sum0 += __shfl_xor_sync(~0u, sum0, 2);
        sum1 += __shfl_xor_sync(~0u, sum1, 1);
        sum1 += __shfl_xor_sync(~0u, sum1, 2);
        l0 = l0 * c0 + sum0; l1 = l1 * c1 + sum1;
        m0 = mn0; m1 = mn1;
#pragma unroll
        for (int nt = 0; nt < 8; nt++) {
            o[nt][0] *= c0; o[nt][1] *= c0;
            o[nt][2] *= c1; o[nt][3] *= c1;
        }

        // ---- pack P into hi/lo A-fragments ----
        uint32_t pah[4][4], pal[4][4];
#pragma unroll
        for (int j = 0; j < 4; j++) {
#pragma unroll
            for (int e = 0; e < 4; e++) {
                int nt = 2 * j + (e >> 1);
                int li = (e & 1) * 2;
                float v0 = s[nt][li], v1 = s[nt][li + 1];
                __nv_bfloat16 h0 = __float2bfloat16(v0);
                __nv_bfloat16 h1 = __float2bfloat16(v1);
                __nv_bfloat162 hp(h0, h1);
                __nv_bfloat162 lp(__float2bfloat16(v0 - __bfloat162float(h0)),
                                  __float2bfloat16(v1 - __bfloat162float(h1)));
                pah[j][e] = *(uint32_t*)&hp;
                pal[j][e] = *(uint32_t*)&lp;
            }
        }

        // ---- O += P V, 3-pass (V via ldmatrix.trans), pass-major ----
#pragma unroll
        for (int j = 0; j < 4; j++) {
            uint32_t vh4[4][4], vl4[4][4];
#pragma unroll
            for (int g = 0; g < 4; g++) {
                uint32_t rb = (uint32_t)((j * 16 + bit3 * 8 + l7) * 128);
                uint32_t sl = ((uint32_t)((g * 2 + bit4) ^ l7)) << 4;
                ldm4t(vh4[g], kb + 16384 + rb + sl);
                ldm4t(vl4[g], kb + 24576 + rb + sl);
            }
            // pass 1: Ph * Vh  (8 independent)
#pragma unroll
            for (int g = 0; g < 4; g++) {
                mma_bf16(o[2*g],   pah[j], vh4[g][0], vh4[g][1]);
                mma_bf16(o[2*g+1], pah[j], vh4[g][2], vh4[g][3]);
            }
            // pass 2: Ph * Vl
#pragma unroll
            for (int g = 0; g < 4; g++) {
                mma_bf16(o[2*g],   pah[j], vl4[g][0], vl4[g][1]);
                mma_bf16(o[2*g+1], pah[j], vl4[g][2], vl4[g][3]);
            }
            // pass 3: Pl * Vh
#pragma unroll
            for (int g = 0; g < 4; g++) {
                mma_bf16(o[2*g],   pal[j], vh4[g][0], vh4[g][1]);
                mma_bf16(o[2*g+1], pal[j], vh4[g][2], vh4[g][3]);
            }
        }

        __syncthreads();
        if (kt + 2 < nkt) load_kv(kt + 2, kt & 1);
    }

    // ---- epilogue: normalize, query-mask, split-write y ----
    const int gr0 = b * BN_T + row0;
    const float sc0 = (mask[gr0] ? 1.f : 0.f) / l0;
    const float sc1 = (mask[gr0 + 8] ? 1.f : 0.f) / l1;
#pragma unroll
    for (int nt = 0; nt < 8; nt++) {
        int col = h * 64 + nt * 8 + col_in;
        float v0 = o[nt][0] * sc0, v1 = o[nt][1] * sc0;
        float v2 = o[nt][2] * sc1, v3 = o[nt][3] * sc1;
        __nv_bfloat16 h0 = __float2bfloat16(v0), h1 = __float2bfloat16(v1);
        __nv_bfloat16 h2 = __float2bfloat16(v2), h3 = __float2bfloat16(v3);
        __nv_bfloat162 hp0(h0, h1), hp1(h2, h3);
        __nv_bfloat162 lp0(__float2bfloat16(v0 - __bfloat162float(h0)),
                           __float2bfloat16(v1 - __bfloat162float(h1)));
        __nv_bfloat162 lp1(__float2bfloat16(v2 - __bfloat162float(h2)),
                           __float2bfloat16(v3 - __bfloat162float(h3)));
        *(uint32_t*)(yh + (size_t)gr0 * DM + col) = *(uint32_t*)&hp0;
        *(uint32_t*)(yl + (size_t)gr0 * DM + col) = *(uint32_t*)&lp0;
        *(uint32_t*)(yh + (size_t)(gr0 + 8) * DM + col) = *(uint32_t*)&hp1;
        *(uint32_t*)(yl + (size_t)(gr0 + 8) * DM + col) = *(uint32_t*)&lp1;
    }
}

// ---------------------------------------------------------------------------
extern "C" void kernel_launch(void* const* d_in, const int* in_sizes, int n_in,
                              void* d_out, int out_size)
{
    const float* x    = (const float*)d_in[0];
    const int*   mask = (const int*)  d_in[1];
    const float* Wqkv = (const float*)d_in[2];
    const float* bqkv = (const float*)d_in[3];
    const float* Wo   = (const float*)d_in[4];
    const float* bo   = (const float*)d_in[5];
    float* out = (float*)d_out;

    __nv_bfloat16 *xh, *xl, *wqh, *wql, *woh, *wol, *qh, *ql, *yh, *yl;
    cudaGetSymbolAddress((void**)&xh,  g_xh);
    cudaGetSymbolAddress((void**)&xl,  g_xl);
    cudaGetSymbolAddress((void**)&wqh, g_wqkvh);
    cudaGetSymbolAddress((void**)&wql, g_wqkvl);
    cudaGetSymbolAddress((void**)&woh, g_woh);
    cudaGetSymbolAddress((void**)&wol, g_wol);
    cudaGetSymbolAddress((void**)&qh,  g_qkvh);
    cudaGetSymbolAddress((void**)&ql,  g_qkvl);
    cudaGetSymbolAddress((void**)&yh,  g_yh);
    cudaGetSymbolAddress((void**)&yl,  g_yl);

    cudaFuncSetAttribute(gemm_bf16x3<0>,
                         cudaFuncAttributeMaxDynamicSharedMemorySize, GEMM_SMEM);
    cudaFuncSetAttribute(gemm_bf16x3<1>,
                         cudaFuncAttributeMaxDynamicSharedMemorySize, GEMM_SMEM);
    cudaFuncSetAttribute(flash_hmma,
                         cudaFuncAttributeMaxDynamicSharedMemorySize, FSMEM);

    split_bf16<<<(MROWS * DM / 4 + 255) / 256, 256>>>(x, xh, xl, MROWS * DM / 4);
    split_bf16<<<(3 * DM * DM / 4 + 255) / 256, 256>>>(Wqkv, wqh, wql, 3 * DM * DM / 4);
    split_bf16<<<(DM * DM / 4 + 255) / 256, 256>>>(Wo, woh, wol, DM * DM / 4);

    // QKV projection -> split bf16 qkv
    gemm_bf16x3<1><<<dim3(3 * DM / 128, MROWS / 128), 256, GEMM_SMEM>>>(
        xh, xl, wqh, wql, bqkv, nullptr, qh, ql, 3 * DM, DM);

    // Causal flash attention (HMMA) -> split bf16 y
    flash_hmma<<<dim3(16, 4 * NH), 256, FSMEM>>>(qh, ql, mask, yh, yl);

    // Output projection -> fp32 out
    gemm_bf16x3<0><<<dim3(DM / 128, MROWS / 128), 256, GEMM_SMEM>>>(
        yh, yl, woh, wol, bo, out, nullptr, nullptr, DM, DM);
}

// round 7
// speedup vs baseline: 1.0631x; 1.0631x over previous
#include <cuda_runtime.h>
#include <cuda_bf16.h>
#include <cstdint>

#define BN_T 2048
#define DM   1024
#define NH   16
#define HD   64
#define MROWS 8192   // B*T

// ---------------------------------------------------------------------------
// Device-global scratch (allocation-free per harness rules)
// ---------------------------------------------------------------------------
__device__ __align__(16) __nv_bfloat16 g_xh[MROWS * DM];
__device__ __align__(16) __nv_bfloat16 g_xl[MROWS * DM];
__device__ __align__(16) __nv_bfloat16 g_wqkvh[3 * DM * DM];
__device__ __align__(16) __nv_bfloat16 g_wqkvl[3 * DM * DM];
__device__ __align__(16) __nv_bfloat16 g_woh[DM * DM];
__device__ __align__(16) __nv_bfloat16 g_wol[DM * DM];
__device__ __align__(16) __nv_bfloat16 g_qkvh[MROWS * 3 * DM];
__device__ __align__(16) __nv_bfloat16 g_qkvl[MROWS * 3 * DM];
__device__ __align__(16) __nv_bfloat16 g_yh[MROWS * DM];
__device__ __align__(16) __nv_bfloat16 g_yl[MROWS * DM];

// ---------------------------------------------------------------------------
// PTX helpers (baseline PTX only: cp.async + ldmatrix + mma.sync)
// ---------------------------------------------------------------------------
__device__ __forceinline__ uint32_t smem_u32(const void* p) {
    uint32_t a;
    asm("{ .reg .u64 t; cvta.to.shared.u64 t, %1; cvt.u32.u64 %0, t; }"
        : "=r"(a) : "l"(p));
    return a;
}

__device__ __forceinline__ void cp_async16(uint32_t saddr, const void* gaddr) {
    asm volatile("cp.async.cg.shared.global [%0], [%1], 16;"
                 :: "r"(saddr), "l"(gaddr) : "memory");
}
#define CP_COMMIT() asm volatile("cp.async.commit_group;" ::: "memory")
#define CP_WAIT(n)  asm volatile("cp.async.wait_group %0;" :: "n"(n) : "memory")

__device__ __forceinline__ void ldm4(uint32_t* r, uint32_t addr) {
    asm volatile("ldmatrix.sync.aligned.m8n8.x4.shared.b16 {%0,%1,%2,%3}, [%4];"
                 : "=r"(r[0]), "=r"(r[1]), "=r"(r[2]), "=r"(r[3]) : "r"(addr));
}
__device__ __forceinline__ void ldm4t(uint32_t* r, uint32_t addr) {
    asm volatile("ldmatrix.sync.aligned.m8n8.x4.trans.shared.b16 {%0,%1,%2,%3}, [%4];"
                 : "=r"(r[0]), "=r"(r[1]), "=r"(r[2]), "=r"(r[3]) : "r"(addr));
}

__device__ __forceinline__ void mma_bf16(float* d, const uint32_t* a,
                                         uint32_t b0, uint32_t b1) {
    asm volatile(
        "mma.sync.aligned.m16n8k16.row.col.f32.bf16.bf16.f32 "
        "{%0,%1,%2,%3}, {%4,%5,%6,%7}, {%8,%9}, {%0,%1,%2,%3};"
        : "+f"(d[0]), "+f"(d[1]), "+f"(d[2]), "+f"(d[3])
        : "r"(a[0]), "r"(a[1]), "r"(a[2]), "r"(a[3]), "r"(b0), "r"(b1));
}

// ---------------------------------------------------------------------------
// fp32 -> (hi, lo) bf16 split, 4 elems/thread
// ---------------------------------------------------------------------------
__global__ __launch_bounds__(256) void split_bf16(
    const float* __restrict__ in,
    __nv_bfloat16* __restrict__ hi,
    __nv_bfloat16* __restrict__ lo,
    int n4)
{
    int i = blockIdx.x * blockDim.x + threadIdx.x;
    if (i >= n4) return;
    float4 v = ((const float4*)in)[i];
    __nv_bfloat16 h0 = __float2bfloat16(v.x);
    __nv_bfloat16 h1 = __float2bfloat16(v.y);
    __nv_bfloat16 h2 = __float2bfloat16(v.z);
    __nv_bfloat16 h3 = __float2bfloat16(v.w);
    __nv_bfloat16 l0 = __float2bfloat16(v.x - __bfloat162float(h0));
    __nv_bfloat16 l1 = __float2bfloat16(v.y - __bfloat162float(h1));
    __nv_bfloat16 l2 = __float2bfloat16(v.z - __bfloat162float(h2));
    __nv_bfloat16 l3 = __float2bfloat16(v.w - __bfloat162float(h3));
    __nv_bfloat162 hp0(h0, h1), hp1(h2, h3), lp0(l0, l1), lp1(l2, l3);
    ((__nv_bfloat162*)hi)[i * 2]     = hp0;
    ((__nv_bfloat162*)hi)[i * 2 + 1] = hp1;
    ((__nv_bfloat162*)lo)[i * 2]     = lp0;
    ((__nv_bfloat162*)lo)[i * 2 + 1] = lp1;
}

// ---------------------------------------------------------------------------
// C = A @ B^T + bias, split bf16 3-pass HMMA.
// 512 threads, warp grid 4x4, warp tile 32x32, CTA tile 128x128, BK=32,
// 3-stage cp.async pipeline (one barrier per chunk).
// OUTM=0: fp32 C.  OUTM=1: split bf16 (Ch, Cl).
// ---------------------------------------------------------------------------
#define STAGE_BYTES 32768
#define GEMM_SMEM  (3 * STAGE_BYTES)

__device__ __forceinline__ uint32_t sw_off(int row, int c) {
    return (uint32_t)(row * 64 + ((c ^ ((row >> 1) & 3)) * 16));
}

template<int OUTM>
__global__ __launch_bounds__(512, 1) void gemm_bf16x3(
    const __nv_bfloat16* __restrict__ Ah, const __nv_bfloat16* __restrict__ Al,
    const __nv_bfloat16* __restrict__ Bh, const __nv_bfloat16* __restrict__ Bl,
    const float* __restrict__ bias,
    float* __restrict__ C,
    __nv_bfloat16* __restrict__ Ch, __nv_bfloat16* __restrict__ Cl,
    int N, int K)
{
    extern __shared__ char smem[];
    const uint32_t sb = smem_u32(smem);
    const int tid = threadIdx.x;
    const int lane = tid & 31;
    const int wid = tid >> 5;           // 0..15
    const int warpM = wid & 3;          // M slice: warpM*32
    const int warpN = wid >> 2;         // N slice: warpN*32
    const int bm = blockIdx.y * 128;
    const int bn = blockIdx.x * 128;
    const int NC = K >> 5;

    const int g  = lane >> 3;
    const int l7 = lane & 7;
    const int arow = (g & 1) * 8 + l7;
    const int acg  = g >> 1;
    const int brow = (g >> 1) * 8 + l7;
    const int bcg  = g & 1;

    uint32_t aRow[2], aSw[2];
#pragma unroll
    for (int mt = 0; mt < 2; mt++) {
        int r = warpM * 32 + mt * 16 + arow;
        aRow[mt] = (uint32_t)(r * 64);
        aSw[mt] = (uint32_t)((r >> 1) & 3);
    }
    uint32_t bRow[2], bSw[2];
#pragma unroll
    for (int ng = 0; ng < 2; ng++) {
        int r = warpN * 32 + ng * 16 + brow;
        bRow[ng] = (uint32_t)(r * 64);
        bSw[ng] = (uint32_t)((r >> 1) & 3);
    }

    float acc[2][4][4];
#pragma unroll
    for (int mt = 0; mt < 2; mt++)
#pragma unroll
        for (int nt = 0; nt < 4; nt++)
#pragma unroll
            for (int e = 0; e < 4; e++) acc[mt][nt][e] = 0.f;

    const __nv_bfloat16* srcA[2] = { Ah + (size_t)bm * K, Al + (size_t)bm * K };
    const __nv_bfloat16* srcB[2] = { Bh + (size_t)bn * K, Bl + (size_t)bn * K };

    auto load_stage = [&](int kc, int st) {
        const uint32_t stbase = sb + st * STAGE_BYTES;
#pragma unroll
        for (int q = 0; q < 4; q++) {
            int cid = tid + q * 512;          // 0..2047
            int sub = cid >> 9;               // 0:Ah 1:Al 2:Bh 3:Bl
            int ci  = cid & 511;
            int row = ci >> 2;
            int c   = ci & 3;
            uint32_t saddr = stbase + sub * 8192 + sw_off(row, c);
            const __nv_bfloat16* gp =
                (sub < 2 ? srcA[sub] : srcB[sub - 2])
                + (size_t)row * K + kc * 32 + c * 8;
            cp_async16(saddr, gp);
        }
        CP_COMMIT();
    };

    load_stage(0, 0);
    load_stage(1, 1);

    for (int i = 0; i < NC; i++) {
        if (i < NC - 1) { CP_WAIT(1); } else { CP_WAIT(0); }
        __syncthreads();    // stage i%3 visible to all; stage (i-1)%3 fully read

        const uint32_t stbase = sb + (i % 3) * STAGE_BYTES;
#pragma unroll
        for (int ks = 0; ks < 2; ks++) {
            uint32_t ah[2][4], al[2][4];
#pragma unroll
            for (int mt = 0; mt < 2; mt++) {
                uint32_t slot = (uint32_t)((2 * ks + acg) ^ aSw[mt]) * 16;
                ldm4(ah[mt], stbase + 0    + aRow[mt] + slot);
                ldm4(al[mt], stbase + 8192 + aRow[mt] + slot);
            }
            uint32_t bh[2][4], bl[2][4];
#pragma unroll
            for (int ng = 0; ng < 2; ng++) {
                uint32_t slot = (uint32_t)((2 * ks + bcg) ^ bSw[ng]) * 16;
                ldm4(bh[ng], stbase + 16384 + bRow[ng] + slot);
                ldm4(bl[ng], stbase + 24576 + bRow[ng] + slot);
            }
#pragma unroll
            for (int mt = 0; mt < 2; mt++)
#pragma unroll
                for (int ng = 0; ng < 2; ng++) {
                    mma_bf16(acc[mt][2 * ng],     ah[mt], bh[ng][0], bh[ng][1]);
                    mma_bf16(acc[mt][2 * ng + 1], ah[mt], bh[ng][2], bh[ng][3]);
                }
#pragma unroll
            for (int mt = 0; mt < 2; mt++)
#pragma unroll
                for (int ng = 0; ng < 2; ng++) {
                    mma_bf16(acc[mt][2 * ng],     ah[mt], bl[ng][0], bl[ng][1]);
                    mma_bf16(acc[mt][2 * ng + 1], ah[mt], bl[ng][2], bl[ng][3]);
                }
#pragma unroll
            for (int mt = 0; mt < 2; mt++)
#pragma unroll
                for (int ng = 0; ng < 2; ng++) {
                    mma_bf16(acc[mt][2 * ng],     al[mt], bh[ng][0], bh[ng][1]);
                    mma_bf16(acc[mt][2 * ng + 1], al[mt], bh[ng][2], bh[ng][3]);
                }
        }

        // No barrier here: stage (i+2)%3 == (i-1)%3 was fully consumed before
        // the barrier at the top of this iteration.
        if (i + 2 < NC) load_stage(i + 2, (i + 2) % 3);
    }

#pragma unroll
    for (int mt = 0; mt < 2; mt++) {
#pragma unroll
        for (int nt = 0; nt < 4; nt++) {
            int row0 = bm + warpM * 32 + mt * 16 + (lane >> 2);
            int col  = bn + warpN * 32 + nt * 8 + (lane & 3) * 2;
            float b0 = bias[col], b1 = bias[col + 1];
            float v0 = acc[mt][nt][0] + b0, v1 = acc[mt][nt][1] + b1;
            float v2 = acc[mt][nt][2] + b0, v3 = acc[mt][nt][3] + b1;
            if (OUTM == 0) {
                float2 p0 = { v0, v1 }, p1 = { v2, v3 };
                *(float2*)(C + (size_t)row0 * N + col) = p0;
                *(float2*)(C + (size_t)(row0 + 8) * N + col) = p1;
            } else {
                __nv_bfloat16 h0 = __float2bfloat16(v0), h1 = __float2bfloat16(v1);
                __nv_bfloat16 h2 = __float2bfloat16(v2), h3 = __float2bfloat16(v3);
                __nv_bfloat162 hp0(h0, h1), hp1(h2, h3);
                __nv_bfloat162 lp0(__float2bfloat16(v0 - __bfloat162float(h0)),
                                   __float2bfloat16(v1 - __bfloat162float(h1)));
                __nv_bfloat162 lp1(__float2bfloat16(v2 - __bfloat162float(h2)),
                                   __float2bfloat16(v3 - __bfloat162float(h3)));
                *(uint32_t*)(Ch + (size_t)row0 * N + col) = *(uint32_t*)&hp0;
                *(uint32_t*)(Cl + (size_t)row0 * N + col) = *(uint32_t*)&lp0;
                *(uint32_t*)(Ch + (size_t)(row0 + 8) * N + col) = *(uint32_t*)&hp1;
                *(uint32_t*)(Cl + (size_t)(row0 + 8) * N + col) = *(uint32_t*)&lp1;
            }
        }
    }
}

// ---------------------------------------------------------------------------
// Causal flash attention, bf16x3 HMMA (unchanged from R6).
// grid (16, B*NH); CTA: 128-query tile for one (b,h); 256 threads / 8 warps.
// ---------------------------------------------------------------------------
#define FSMEM (32768 + 2 * 32768)   // Qh|Ql (32K) + 2 stages of Kh|Kl|Vh|Vl

__global__ __launch_bounds__(256, 1) void flash_hmma(
    const __nv_bfloat16* __restrict__ qkvh,
    const __nv_bfloat16* __restrict__ qkvl,
    const int* __restrict__ mask,
    __nv_bfloat16* __restrict__ yh,
    __nv_bfloat16* __restrict__ yl)
{
    extern __shared__ char smem[];
    const uint32_t sb = smem_u32(smem);
    const int tid = threadIdx.x;
    const int lane = tid & 31, wid = tid >> 5;
    const int qt = 15 - (int)blockIdx.x;          // descending work order
    const int bh = blockIdx.y, b = bh >> 4, h = bh & 15;
    const int nkt = 2 * qt + 2;
    const int l7 = lane & 7, bit3 = (lane >> 3) & 1, bit4 = (lane >> 4) & 1;

    const uint32_t QH = sb, QL = sb + 16384, ST = sb + 32768;

    // Q load: 128 rows x 128B x {h,l}
    {
        const size_t rq = (size_t)(b * BN_T + qt * 128);
#pragma unroll
        for (int q = 0; q < 8; q++) {
            int cid = q * 256 + tid;
            int arr = cid >> 10, ci = cid & 1023, row = ci >> 3, c = ci & 7;
            const __nv_bfloat16* gp = (arr ? qkvl : qkvh)
                + (rq + row) * 3072 + h * 64 + c * 8;
            cp_async16(sb + arr * 16384 + row * 128 + (((c ^ (row & 7))) << 4), gp);
        }
        CP_COMMIT();
    }

    auto load_kv = [&](int kt, int st) {
        const uint32_t base = ST + st * 32768;
        const size_t rk = (size_t)(b * BN_T + kt * 64);
#pragma unroll
        for (int q = 0; q < 8; q++) {
            int cid = q * 256 + tid;
            int sub = cid >> 9, ci = cid & 511, row = ci >> 3, c = ci & 7;
            const __nv_bfloat16* src = (sub & 1) ? qkvl : qkvh;
            int colb = (sub >> 1) ? (2048 + h * 64) : (1024 + h * 64);
            const __nv_bfloat16* gp = src + (rk + row) * 3072 + colb + c * 8;
            cp_async16(base + sub * 8192 + row * 128 + (((c ^ (row & 7))) << 4), gp);
        }
        CP_COMMIT();
    };

    load_kv(0, 0);
    load_kv(1, 1);

    CP_WAIT(2);            // Q resident
    __syncthreads();

    // Q fragments (register-resident)
    uint32_t qhf[4][4], qlf[4][4];
    {
        const uint32_t rb = (uint32_t)((wid * 16 + bit3 * 8 + l7) * 128);
#pragma unroll
        for (int ks = 0; ks < 4; ks++) {
            uint32_t sl = ((uint32_t)((ks * 2 + bit4) ^ l7)) << 4;
            ldm4(qhf[ks], QH + rb + sl);
            ldm4(qlf[ks], QL + rb + sl);
        }
    }

    float o[8][4];
#pragma unroll
    for (int nt = 0; nt < 8; nt++)
#pragma unroll
        for (int e = 0; e < 4; e++) o[nt][e] = 0.f;
    float m0 = -1e30f, m1 = -1e30f, l0 = 0.f, l1 = 0.f;

    const int row0 = qt * 128 + wid * 16 + (lane >> 2);
    const int col_in = (lane & 3) * 2;

    for (int kt = 0; kt < nkt; kt++) {
        if (kt + 1 < nkt) { CP_WAIT(1); } else { CP_WAIT(0); }
        __syncthreads();
        const uint32_t kb = ST + (kt & 1) * 32768;

        // ---- S = (Q Kᵀ) * 0.125, 3-pass ----
        float s[8][4];
#pragma unroll
        for (int nt = 0; nt < 8; nt++)
#pragma unroll
            for (int e = 0; e < 4; e++) s[nt][e] = 0.f;

#pragma unroll
        for (int ks = 0; ks < 4; ks++) {
            uint32_t kh4[4][4], kl4[4][4];
#pragma unroll
            for (int np = 0; np < 4; np++) {
                uint32_t rb = (uint32_t)((np * 16 + bit4 * 8 + l7) * 128);
                uint32_t sl = ((uint32_t)((ks * 2 + bit3) ^ l7)) << 4;
                ldm4(kh4[np], kb + rb + sl);
                ldm4(kl4[np], kb + 8192 + rb + sl);
            }
#pragma unroll
            for (int np = 0; np < 4; np++) {
                mma_bf16(s[2*np],   qhf[ks], kh4[np][0], kh4[np][1]);
                mma_bf16(s[2*np+1], qhf[ks], kh4[np][2], kh4[np][3]);
            }
#pragma unroll
            for (int np = 0; np < 4; np++) {
                mma_bf16(s[2*np],   qhf[ks], kl4[np][0], kl4[np][1]);
                mma_bf16(s[2*np+1], qhf[ks], kl4[np][2], kl4[np][3]);
            }
#pragma unroll
            for (int np = 0; np < 4; np++) {
                mma_bf16(s[2*np],   qlf[ks], kh4[np][0], kh4[np][1]);
                mma_bf16(s[2*np+1], qlf[ks], kh4[np][2], kh4[np][3]);
            }
        }

        const bool diag = (kt >= 2 * qt);
#pragma unroll
        for (int nt = 0; nt < 8; nt++) {
#pragma unroll
            for (int e = 0; e < 4; e++) s[nt][e] *= 0.125f;
            if (diag) {
                int key = kt * 64 + nt * 8 + col_in;
                if (key     > row0)     s[nt][0] = -1e30f;
                if (key + 1 > row0)     s[nt][1] = -1e30f;
                if (key     > row0 + 8) s[nt][2] = -1e30f;
                if (key + 1 > row0 + 8) s[nt][3] = -1e30f;
            }
        }

        // ---- online softmax ----
        float rm0 = s[0][0], rm1 = s[0][2];
#pragma unroll
        for (int nt = 0; nt < 8; nt++) {
            rm0 = fmaxf(rm0, fmaxf(s[nt][0], s[nt][1]));
            rm1 = fmaxf(rm1, fmaxf(s[nt][2], s[nt][3]));
        }
        rm0 = fmaxf(rm0, __shfl_xor_sync(~0u, rm0, 1));
        rm0 = fmaxf(rm0, __shfl_xor_sync(~0u, rm0, 2));
        rm1 = fmaxf(rm1, __shfl_xor_sync(~0u, rm1, 1));
        rm1 = fmaxf(rm1, __shfl_xor_sync(~0u, rm1, 2));
        float mn0 = fmaxf(m0, rm0), mn1 = fmaxf(m1, rm1);
        float c0 = __expf(m0 - mn0), c1 = __expf(m1 - mn1);
        float sum0 = 0.f, sum1 = 0.f;
#pragma unroll
        for (int nt = 0; nt < 8; nt++) {
            s[nt][0] = __expf(s[nt][0] - mn0);
            s[nt][1] = __expf(s[nt][1] - mn0);
            s[nt][2] = __expf(s[nt][2] - mn1);
            s[nt][3] = __expf(s[nt][3] - mn1);
            sum0 += s[nt][0] + s[nt][1];
            sum1 += s[nt][2] + s[nt][3];
        }
        sum0 += __shfl_xor_sync(~0u, sum0, 1);
        sum0 += __shfl_xor_sync(~0u, sum0, 2);
        sum1 += __shfl_xor_sync(~0u, sum1, 1);
        sum1 += __shfl_xor_sync(~0u, sum1, 2);
        l0 = l0 * c0 + sum0; l1 = l1 * c1 + sum1;
        m0 = mn0; m1 = mn1;
#pragma unroll
        for (int nt = 0; nt < 8; nt++) {
            o[nt][0] *= c0; o[nt][1] *= c0;
            o[nt][2] *= c1; o[nt][3] *= c1;
        }

        // ---- pack P into hi/lo A-fragments ----
        uint32_t pah[4][4], pal[4][4];
#pragma unroll
        for (int j = 0; j < 4; j++) {
#pragma unroll
            for (int e = 0; e < 4; e++) {
                int nt = 2 * j + (e >> 1);
                int li = (e & 1) * 2;
                float v0 = s[nt][li], v1 = s[nt][li + 1];
                __nv_bfloat16 h0 = __float2bfloat16(v0);
                __nv_bfloat16 h1 = __float2bfloat16(v1);
                __nv_bfloat162 hp(h0, h1);
                __nv_bfloat162 lp(__float2bfloat16(v0 - __bfloat162float(h0)),
                                  __float2bfloat16(v1 - __bfloat162float(h1)));
                pah[j][e] = *(uint32_t*)&hp;
                pal[j][e] = *(uint32_t*)&lp;
            }
        }

        // ---- O += P V, 3-pass (V via ldmatrix.trans) ----
#pragma unroll
        for (int j = 0; j < 4; j++) {
            uint32_t vh4[4][4], vl4[4][4];
#pragma unroll
            for (int g = 0; g < 4; g++) {
                uint32_t rb = (uint32_t)((j * 16 + bit3 * 8 + l7) * 128);
                uint32_t sl = ((uint32_t)((g * 2 + bit4) ^ l7)) << 4;
                ldm4t(vh4[g], kb + 16384 + rb + sl);
                ldm4t(vl4[g], kb + 24576 + rb + sl);
            }
#pragma unroll
            for (int g = 0; g < 4; g++) {
                mma_bf16(o[2*g],   pah[j], vh4[g][0], vh4[g][1]);
                mma_bf16(o[2*g+1], pah[j], vh4[g][2], vh4[g][3]);
            }
#pragma unroll
            for (int g = 0; g < 4; g++) {
                mma_bf16(o[2*g],   pah[j], vl4[g][0], vl4[g][1]);
                mma_bf16(o[2*g+1], pah[j], vl4[g][2], vl4[g][3]);
            }
#pragma unroll
            for (int g = 0; g < 4; g++) {
                mma_bf16(o[2*g],   pal[j], vh4[g][0], vh4[g][1]);
                mma_bf16(o[2*g+1], pal[j], vh4[g][2], vh4[g][3]);
            }
        }

        __syncthreads();
        if (kt + 2 < nkt) load_kv(kt + 2, kt & 1);
    }

    // ---- epilogue: normalize, query-mask, split-write y ----
    const int gr0 = b * BN_T + row0;
    const float sc0 = (mask[gr0] ? 1.f : 0.f) / l0;
    const float sc1 = (mask[gr0 + 8] ? 1.f : 0.f) / l1;
#pragma unroll
    for (int nt = 0; nt < 8; nt++) {
        int col = h * 64 + nt * 8 + col_in;
        float v0 = o[nt][0] * sc0, v1 = o[nt][1] * sc0;
        float v2 = o[nt][2] * sc1, v3 = o[nt][3] * sc1;
        __nv_bfloat16 h0 = __float2bfloat16(v0), h1 = __float2bfloat16(v1);
        __nv_bfloat16 h2 = __float2bfloat16(v2), h3 = __float2bfloat16(v3);
        __nv_bfloat162 hp0(h0, h1), hp1(h2, h3);
        __nv_bfloat162 lp0(__float2bfloat16(v0 - __bfloat162float(h0)),
                           __float2bfloat16(v1 - __bfloat162float(h1)));
        __nv_bfloat162 lp1(__float2bfloat16(v2 - __bfloat162float(h2)),
                           __float2bfloat16(v3 - __bfloat162float(h3)));
        *(uint32_t*)(yh + (size_t)gr0 * DM + col) = *(uint32_t*)&hp0;
        *(uint32_t*)(yl + (size_t)gr0 * DM + col) = *(uint32_t*)&lp0;
        *(uint32_t*)(yh + (size_t)(gr0 + 8) * DM + col) = *(uint32_t*)&hp1;
        *(uint32_t*)(yl + (size_t)(gr0 + 8) * DM + col) = *(uint32_t*)&lp1;
    }
}

// ---------------------------------------------------------------------------
extern "C" void kernel_launch(void* const* d_in, const int* in_sizes, int n_in,
                              void* d_out, int out_size)
{
    const float* x    = (const float*)d_in[0];
    const int*   mask = (const int*)  d_in[1];
    const float* Wqkv = (const float*)d_in[2];
    const float* bqkv = (const float*)d_in[3];
    const float* Wo   = (const float*)d_in[4];
    const float* bo   = (const float*)d_in[5];
    float* out = (float*)d_out;

    __nv_bfloat16 *xh, *xl, *wqh, *wql, *woh, *wol, *qh, *ql, *yh, *yl;
    cudaGetSymbolAddress((void**)&xh,  g_xh);
    cudaGetSymbolAddress((void**)&xl,  g_xl);
    cudaGetSymbolAddress((void**)&wqh, g_wqkvh);
    cudaGetSymbolAddress((void**)&wql, g_wqkvl);
    cudaGetSymbolAddress((void**)&woh, g_woh);
    cudaGetSymbolAddress((void**)&wol, g_wol);
    cudaGetSymbolAddress((void**)&qh,  g_qkvh);
    cudaGetSymbolAddress((void**)&ql,  g_qkvl);
    cudaGetSymbolAddress((void**)&yh,  g_yh);
    cudaGetSymbolAddress((void**)&yl,  g_yl);

    cudaFuncSetAttribute(gemm_bf16x3<0>,
                         cudaFuncAttributeMaxDynamicSharedMemorySize, GEMM_SMEM);
    cudaFuncSetAttribute(gemm_bf16x3<1>,
                         cudaFuncAttributeMaxDynamicSharedMemorySize, GEMM_SMEM);
    cudaFuncSetAttribute(flash_hmma,
                         cudaFuncAttributeMaxDynamicSharedMemorySize, FSMEM);

    split_bf16<<<(MROWS * DM / 4 + 255) / 256, 256>>>(x, xh, xl, MROWS * DM / 4);
    split_bf16<<<(3 * DM * DM / 4 + 255) / 256, 256>>>(Wqkv, wqh, wql, 3 * DM * DM / 4);
    split_bf16<<<(DM * DM / 4 + 255) / 256, 256>>>(Wo, woh, wol, DM * DM / 4);

    // QKV projection -> split bf16 qkv
    gemm_bf16x3<1><<<dim3(3 * DM / 128, MROWS / 128), 512, GEMM_SMEM>>>(
        xh, xl, wqh, wql, bqkv, nullptr, qh, ql, 3 * DM, DM);

    // Causal flash attention (HMMA) -> split bf16 y
    flash_hmma<<<dim3(16, 4 * NH), 256, FSMEM>>>(qh, ql, mask, yh, yl);

    // Output projection -> fp32 out
    gemm_bf16x3<0><<<dim3(DM / 128, MROWS / 128), 512, GEMM_SMEM>>>(
        yh, yl, woh, wol, bo, out, nullptr, nullptr, DM, DM);
}

// round 9
// speedup vs baseline: 2.1556x; 2.0277x over previous
#include <cuda_runtime.h>
#include <cuda_fp16.h>
#include <cstdint>

#define BN_T 2048
#define DM   1024
#define NH   16
#define HD   64
#define MROWS 8192   // B*T

// ---------------------------------------------------------------------------
// Device-global scratch (allocation-free per harness rules)
// ---------------------------------------------------------------------------
__device__ __align__(16) __half g_x16[MROWS * DM];
__device__ __align__(16) __half g_wqkv16[3 * DM * DM];
__device__ __align__(16) __half g_wo16[DM * DM];
__device__ __align__(16) __half g_qkv16[MROWS * 3 * DM];
__device__ __align__(16) __half g_y16[MROWS * DM];

// ---------------------------------------------------------------------------
// PTX helpers (baseline PTX only: cp.async + ldmatrix + mma.sync)
// ---------------------------------------------------------------------------
__device__ __forceinline__ uint32_t smem_u32(const void* p) {
    uint32_t a;
    asm("{ .reg .u64 t; cvta.to.shared.u64 t, %1; cvt.u32.u64 %0, t; }"
        : "=r"(a) : "l"(p));
    return a;
}

__device__ __forceinline__ void cp_async16(uint32_t saddr, const void* gaddr) {
    asm volatile("cp.async.cg.shared.global [%0], [%1], 16;"
                 :: "r"(saddr), "l"(gaddr) : "memory");
}
#define CP_COMMIT() asm volatile("cp.async.commit_group;" ::: "memory")
#define CP_WAIT(n)  asm volatile("cp.async.wait_group %0;" :: "n"(n) : "memory")

__device__ __forceinline__ void ldm4(uint32_t* r, uint32_t addr) {
    asm volatile("ldmatrix.sync.aligned.m8n8.x4.shared.b16 {%0,%1,%2,%3}, [%4];"
                 : "=r"(r[0]), "=r"(r[1]), "=r"(r[2]), "=r"(r[3]) : "r"(addr));
}
__device__ __forceinline__ void ldm4t(uint32_t* r, uint32_t addr) {
    asm volatile("ldmatrix.sync.aligned.m8n8.x4.trans.shared.b16 {%0,%1,%2,%3}, [%4];"
                 : "=r"(r[0]), "=r"(r[1]), "=r"(r[2]), "=r"(r[3]) : "r"(addr));
}

__device__ __forceinline__ void mma_f16(float* d, const uint32_t* a,
                                        uint32_t b0, uint32_t b1) {
    asm volatile(
        "mma.sync.aligned.m16n8k16.row.col.f32.f16.f16.f32 "
        "{%0,%1,%2,%3}, {%4,%5,%6,%7}, {%8,%9}, {%0,%1,%2,%3};"
        : "+f"(d[0]), "+f"(d[1]), "+f"(d[2]), "+f"(d[3])
        : "r"(a[0]), "r"(a[1]), "r"(a[2]), "r"(a[3]), "r"(b0), "r"(b1));
}

// ---------------------------------------------------------------------------
// fp32 -> fp16 convert, 4 elems/thread
// ---------------------------------------------------------------------------
__global__ __launch_bounds__(256) void cvt_f16(
    const float* __restrict__ in, __half* __restrict__ out, int n4)
{
    int i = blockIdx.x * blockDim.x + threadIdx.x;
    if (i >= n4) return;
    float4 v = ((const float4*)in)[i];
    __half2 p0 = __floats2half2_rn(v.x, v.y);
    __half2 p1 = __floats2half2_rn(v.z, v.w);
    ((__half2*)out)[i * 2]     = p0;
    ((__half2*)out)[i * 2 + 1] = p1;
}

// ---------------------------------------------------------------------------
// C = A @ B^T + bias, 1-pass fp16 HMMA, fp32 accumulate.
// 512 threads, warp grid 4x4, warp tile 32x32, CTA tile 128x128, BK=32,
// 3-stage cp.async pipeline.
// OUTM=0: fp32 C.  OUTM=1: fp16 Ch.
// ---------------------------------------------------------------------------
#define STAGE_BYTES 16384          // A 8KB | B 8KB
#define GEMM_SMEM  (3 * STAGE_BYTES)

__device__ __forceinline__ uint32_t sw_off(int row, int c) {
    return (uint32_t)(row * 64 + ((c ^ ((row >> 1) & 3)) * 16));
}

template<int OUTM>
__global__ __launch_bounds__(512, 1) void gemm_f16(
    const __half* __restrict__ Ah, const __half* __restrict__ Bh,
    const float* __restrict__ bias,
    float* __restrict__ C, __half* __restrict__ Ch,
    int N, int K)
{
    extern __shared__ char smem[];
    const uint32_t sb = smem_u32(smem);
    const int tid = threadIdx.x;
    const int lane = tid & 31;
    const int wid = tid >> 5;           // 0..15
    const int warpM = wid & 3;
    const int warpN = wid >> 2;
    const int bm = blockIdx.y * 128;
    const int bn = blockIdx.x * 128;
    const int NC = K >> 5;

    const int g  = lane >> 3;
    const int l7 = lane & 7;
    const int arow = (g & 1) * 8 + l7;
    const int acg  = g >> 1;
    const int brow = (g >> 1) * 8 + l7;
    const int bcg  = g & 1;

    uint32_t aRow[2], aSw[2];
#pragma unroll
    for (int mt = 0; mt < 2; mt++) {
        int r = warpM * 32 + mt * 16 + arow;
        aRow[mt] = (uint32_t)(r * 64);
        aSw[mt] = (uint32_t)((r >> 1) & 3);
    }
    uint32_t bRow[2], bSw[2];
#pragma unroll
    for (int ng = 0; ng < 2; ng++) {
        int r = warpN * 32 + ng * 16 + brow;
        bRow[ng] = (uint32_t)(r * 64);
        bSw[ng] = (uint32_t)((r >> 1) & 3);
    }

    float acc[2][4][4];
#pragma unroll
    for (int mt = 0; mt < 2; mt++)
#pragma unroll
        for (int nt = 0; nt < 4; nt++)
#pragma unroll
            for (int e = 0; e < 4; e++) acc[mt][nt][e] = 0.f;

    const __half* srcA = Ah + (size_t)bm * K;
    const __half* srcB = Bh + (size_t)bn * K;

    auto load_stage = [&](int kc, int st) {
        const uint32_t stbase = sb + st * STAGE_BYTES;
#pragma unroll
        for (int q = 0; q < 2; q++) {
            int cid = tid + q * 512;          // 0..1023
            int sub = cid >> 9;               // 0:A 1:B
            int ci  = cid & 511;
            int row = ci >> 2;
            int c   = ci & 3;
            uint32_t saddr = stbase + sub * 8192 + sw_off(row, c);
            const __half* gp = (sub ? srcB : srcA)
                + (size_t)row * K + kc * 32 + c * 8;
            cp_async16(saddr, gp);
        }
        CP_COMMIT();
    };

    load_stage(0, 0);
    load_stage(1, 1);

    for (int i = 0; i < NC; i++) {
        if (i < NC - 1) { CP_WAIT(1); } else { CP_WAIT(0); }
        __syncthreads();

        const uint32_t stbase = sb + (i % 3) * STAGE_BYTES;
#pragma unroll
        for (int ks = 0; ks < 2; ks++) {
            uint32_t a[2][4], b[2][4];
#pragma unroll
            for (int mt = 0; mt < 2; mt++) {
                uint32_t slot = (uint32_t)((2 * ks + acg) ^ aSw[mt]) * 16;
                ldm4(a[mt], stbase + aRow[mt] + slot);
            }
#pragma unroll
            for (int ng = 0; ng < 2; ng++) {
                uint32_t slot = (uint32_t)((2 * ks + bcg) ^ bSw[ng]) * 16;
                ldm4(b[ng], stbase + 8192 + bRow[ng] + slot);
            }
#pragma unroll
            for (int mt = 0; mt < 2; mt++)
#pragma unroll
                for (int ng = 0; ng < 2; ng++) {
                    mma_f16(acc[mt][2 * ng],     a[mt], b[ng][0], b[ng][1]);
                    mma_f16(acc[mt][2 * ng + 1], a[mt], b[ng][2], b[ng][3]);
                }
        }

        // stage (i+2)%3 == (i-1)%3 was fully consumed before this iter's barrier
        if (i + 2 < NC) load_stage(i + 2, (i + 2) % 3);
    }

#pragma unroll
    for (int mt = 0; mt < 2; mt++) {
#pragma unroll
        for (int nt = 0; nt < 4; nt++) {
            int row0 = bm + warpM * 32 + mt * 16 + (lane >> 2);
            int col  = bn + warpN * 32 + nt * 8 + (lane & 3) * 2;
            float b0 = bias[col], b1 = bias[col + 1];
            float v0 = acc[mt][nt][0] + b0, v1 = acc[mt][nt][1] + b1;
            float v2 = acc[mt][nt][2] + b0, v3 = acc[mt][nt][3] + b1;
            if (OUTM == 0) {
                float2 p0 = { v0, v1 }, p1 = { v2, v3 };
                *(float2*)(C + (size_t)row0 * N + col) = p0;
                *(float2*)(C + (size_t)(row0 + 8) * N + col) = p1;
            } else {
                __half2 h0 = __floats2half2_rn(v0, v1);
                __half2 h1 = __floats2half2_rn(v2, v3);
                *(__half2*)(Ch + (size_t)row0 * N + col) = h0;
                *(__half2*)(Ch + (size_t)(row0 + 8) * N + col) = h1;
            }
        }
    }
}

// ---------------------------------------------------------------------------
// Causal flash attention, 1-pass fp16 HMMA.
// grid (16, B*NH); CTA: 128-query tile for one (b,h); 256 threads / 8 warps.
// K/V tiles of 64 keys, double-buffered cp.async. Writes fp16 y,
// invalid query rows zeroed.
// ---------------------------------------------------------------------------
#define FSMEM (16384 + 2 * 16384)   // Q (16K) + 2 stages of K|V (16K each)

__global__ __launch_bounds__(256, 1) void flash_f16(
    const __half* __restrict__ qkv,
    const int* __restrict__ mask,
    __half* __restrict__ y)
{
    extern __shared__ char smem[];
    const uint32_t sb = smem_u32(smem);
    const int tid = threadIdx.x;
    const int lane = tid & 31, wid = tid >> 5;
    const int qt = 15 - (int)blockIdx.x;          // descending work order
    const int bh = blockIdx.y, b = bh >> 4, h = bh & 15;
    const int nkt = 2 * qt + 2;
    const int l7 = lane & 7, bit3 = (lane >> 3) & 1, bit4 = (lane >> 4) & 1;

    const uint32_t QB = sb, ST = sb + 16384;

    // Q load: 128 rows x 128B
    {
        const size_t rq = (size_t)(b * BN_T + qt * 128);
#pragma unroll
        for (int q = 0; q < 4; q++) {
            int cid = q * 256 + tid;
            int row = cid >> 3, c = cid & 7;
            const __half* gp = qkv + (rq + row) * 3072 + h * 64 + c * 8;
            cp_async16(QB + row * 128 + (((c ^ (row & 7))) << 4), gp);
        }
        CP_COMMIT();
    }

    auto load_kv = [&](int kt, int st) {
        const uint32_t base = ST + st * 16384;
        const size_t rk = (size_t)(b * BN_T + kt * 64);
#pragma unroll
        for (int q = 0; q < 4; q++) {
            int cid = q * 256 + tid;
            int sub = cid >> 9, ci = cid & 511, row = ci >> 3, c = ci & 7;
            int colb = sub ? (2048 + h * 64) : (1024 + h * 64);
            const __half* gp = qkv + (rk + row) * 3072 + colb + c * 8;
            cp_async16(base + sub * 8192 + row * 128 + (((c ^ (row & 7))) << 4), gp);
        }
        CP_COMMIT();
    };

    load_kv(0, 0);
    load_kv(1, 1);

    CP_WAIT(2);            // Q resident
    __syncthreads();

    // Q fragments (register-resident)
    uint32_t qf[4][4];
    {
        const uint32_t rb = (uint32_t)((wid * 16 + bit3 * 8 + l7) * 128);
#pragma unroll
        for (int ks = 0; ks < 4; ks++) {
            uint32_t sl = ((uint32_t)((ks * 2 + bit4) ^ l7)) << 4;
            ldm4(qf[ks], QB + rb + sl);
        }
    }

    float o[8][4];
#pragma unroll
    for (int nt = 0; nt < 8; nt++)
#pragma unroll
        for (int e = 0; e < 4; e++) o[nt][e] = 0.f;
    float m0 = -1e30f, m1 = -1e30f, l0 = 0.f, l1 = 0.f;

    const int row0 = qt * 128 + wid * 16 + (lane >> 2);
    const int col_in = (lane & 3) * 2;

    for (int kt = 0; kt < nkt; kt++) {
        if (kt + 1 < nkt) { CP_WAIT(1); } else { CP_WAIT(0); }
        __syncthreads();
        const uint32_t kb = ST + (kt & 1) * 16384;

        // ---- S = (Q Kᵀ) * 0.125 ----
        float s[8][4];
#pragma unroll
        for (int nt = 0; nt < 8; nt++)
#pragma unroll
            for (int e = 0; e < 4; e++) s[nt][e] = 0.f;

#pragma unroll
        for (int ks = 0; ks < 4; ks++) {
            uint32_t k4[4][4];
#pragma unroll
            for (int np = 0; np < 4; np++) {
                uint32_t rb = (uint32_t)((np * 16 + bit4 * 8 + l7) * 128);
                uint32_t sl = ((uint32_t)((ks * 2 + bit3) ^ l7)) << 4;
                ldm4(k4[np], kb + rb + sl);
            }
#pragma unroll
            for (int np = 0; np < 4; np++) {
                mma_f16(s[2*np],   qf[ks], k4[np][0], k4[np][1]);
                mma_f16(s[2*np+1], qf[ks], k4[np][2], k4[np][3]);
            }
        }

        const bool diag = (kt >= 2 * qt);
#pragma unroll
        for (int nt = 0; nt < 8; nt++) {
#pragma unroll
            for (int e = 0; e < 4; e++) s[nt][e] *= 0.125f;
            if (diag) {
                int key = kt * 64 + nt * 8 + col_in;
                if (key     > row0)     s[nt][0] = -1e30f;
                if (key + 1 > row0)     s[nt][1] = -1e30f;
                if (key     > row0 + 8) s[nt][2] = -1e30f;
                if (key + 1 > row0 + 8) s[nt][3] = -1e30f;
            }
        }

        // ---- online softmax ----
        float rm0 = s[0][0], rm1 = s[0][2];
#pragma unroll
        for (int nt = 0; nt < 8; nt++) {
            rm0 = fmaxf(rm0, fmaxf(s[nt][0], s[nt][1]));
            rm1 = fmaxf(rm1, fmaxf(s[nt][2], s[nt][3]));
        }
        rm0 = fmaxf(rm0, __shfl_xor_sync(~0u, rm0, 1));
        rm0 = fmaxf(rm0, __shfl_xor_sync(~0u, rm0, 2));
        rm1 = fmaxf(rm1, __shfl_xor_sync(~0u, rm1, 1));
        rm1 = fmaxf(rm1, __shfl_xor_sync(~0u, rm1, 2));
        float mn0 = fmaxf(m0, rm0), mn1 = fmaxf(m1, rm1);
        float c0 = __expf(m0 - mn0), c1 = __expf(m1 - mn1);
        float sum0 = 0.f, sum1 = 0.f;
#pragma unroll
        for (int nt = 0; nt < 8; nt++) {
            s[nt][0] = __expf(s[nt][0] - mn0);
            s[nt][1] = __expf(s[nt][1] - mn0);
            s[nt][2] = __expf(s[nt][2] - mn1);
            s[nt][3] = __expf(s[nt][3] - mn1);
            sum0 += s[nt][0] + s[nt][1];
            sum1 += s[nt][2] + s[nt][3];
        }
        sum0 += __shfl_xor_sync(~0u, sum0, 1);
        sum0 += __shfl_xor_sync(~0u, sum0, 2);
        sum1 += __shfl_xor_sync(~0u, sum1, 1);
        sum1 += __shfl_xor_sync(~0u, sum1, 2);
        l0 = l0 * c0 + sum0; l1 = l1 * c1 + sum1;
        m0 = mn0; m1 = mn1;
#pragma unroll
        for (int nt = 0; nt < 8; nt++) {
            o[nt][0] *= c0; o[nt][1] *= c0;
            o[nt][2] *= c1; o[nt][3] *= c1;
        }

        // ---- pack P into fp16 A-fragments ----
        uint32_t pa[4][4];
#pragma unroll
        for (int j = 0; j < 4; j++) {
#pragma unroll
            for (int e = 0; e < 4; e++) {
                int nt = 2 * j + (e >> 1);
                int li = (e & 1) * 2;
                __half2 hp = __floats2half2_rn(s[nt][li], s[nt][li + 1]);
                pa[j][e] = *(uint32_t*)&hp;
            }
        }

        // ---- O += P V (V via ldmatrix.trans) ----
#pragma unroll
        for (int j = 0; j < 4; j++) {
            uint32_t v4[4][4];
#pragma unroll
            for (int g = 0; g < 4; g++) {
                uint32_t rb = (uint32_t)((j * 16 + bit3 * 8 + l7) * 128);
                uint32_t sl = ((uint32_t)((g * 2 + bit4) ^ l7)) << 4;
                ldm4t(v4[g], kb + 8192 + rb + sl);
            }
#pragma unroll
            for (int g = 0; g < 4; g++) {
                mma_f16(o[2*g],   pa[j], v4[g][0], v4[g][1]);
                mma_f16(o[2*g+1], pa[j], v4[g][2], v4[g][3]);
            }
        }

        __syncthreads();
        if (kt + 2 < nkt) load_kv(kt + 2, kt & 1);
    }

    // ---- epilogue: normalize, query-mask, fp16 write ----
    const int gr0 = b * BN_T + row0;
    const float sc0 = (mask[gr0] ? 1.f : 0.f) / l0;
    const float sc1 = (mask[gr0 + 8] ? 1.f : 0.f) / l1;
#pragma unroll
    for (int nt = 0; nt < 8; nt++) {
        int col = h * 64 + nt * 8 + col_in;
        __half2 h0 = __floats2half2_rn(o[nt][0] * sc0, o[nt][1] * sc0);
        __half2 h1 = __floats2half2_rn(o[nt][2] * sc1, o[nt][3] * sc1);
        *(__half2*)(y + (size_t)gr0 * DM + col) = h0;
        *(__half2*)(y + (size_t)(gr0 + 8) * DM + col) = h1;
    }
}

// ---------------------------------------------------------------------------
extern "C" void kernel_launch(void* const* d_in, const int* in_sizes, int n_in,
                              void* d_out, int out_size)
{
    const float* x    = (const float*)d_in[0];
    const int*   mask = (const int*)  d_in[1];
    const float* Wqkv = (const float*)d_in[2];
    const float* bqkv = (const float*)d_in[3];
    const float* Wo   = (const float*)d_in[4];
    const float* bo   = (const float*)d_in[5];
    float* out = (float*)d_out;

    __half *x16, *wqkv16, *wo16, *qkv16, *y16;
    cudaGetSymbolAddress((void**)&x16,    g_x16);
    cudaGetSymbolAddress((void**)&wqkv16, g_wqkv16);
    cudaGetSymbolAddress((void**)&wo16,   g_wo16);
    cudaGetSymbolAddress((void**)&qkv16,  g_qkv16);
    cudaGetSymbolAddress((void**)&y16,    g_y16);

    cudaFuncSetAttribute(gemm_f16<0>,
                         cudaFuncAttributeMaxDynamicSharedMemorySize, GEMM_SMEM);
    cudaFuncSetAttribute(gemm_f16<1>,
                         cudaFuncAttributeMaxDynamicSharedMemorySize, GEMM_SMEM);
    cudaFuncSetAttribute(flash_f16,
                         cudaFuncAttributeMaxDynamicSharedMemorySize, FSMEM);

    cvt_f16<<<(MROWS * DM / 4 + 255) / 256, 256>>>(x, x16, MROWS * DM / 4);
    cvt_f16<<<(3 * DM * DM / 4 + 255) / 256, 256>>>(Wqkv, wqkv16, 3 * DM * DM / 4);
    cvt_f16<<<(DM * DM / 4 + 255) / 256, 256>>>(Wo, wo16, DM * DM / 4);

    // QKV projection -> fp16 qkv
    gemm_f16<1><<<dim3(3 * DM / 128, MROWS / 128), 512, GEMM_SMEM>>>(
        x16, wqkv16, bqkv, nullptr, qkv16, 3 * DM, DM);

    // Causal flash attention -> fp16 y
    flash_f16<<<dim3(16, 4 * NH), 256, FSMEM>>>(qkv16, mask, y16);

    // Output projection -> fp32 out
    gemm_f16<0><<<dim3(DM / 128, MROWS / 128), 512, GEMM_SMEM>>>(
        y16, wo16, bo, out, nullptr, DM, DM);
}

// round 15
// speedup vs baseline: 2.5116x; 1.1651x over previous
#include <cuda_runtime.h>
#include <cuda_fp16.h>
#include <cstdint>

#define BN_T 2048
#define DM   1024
#define NH   16
#define HD   64
#define MROWS 8192   // B*T

// ---------------------------------------------------------------------------
// Device-global scratch (allocation-free per harness rules)
// ---------------------------------------------------------------------------
__device__ __align__(16) __half g_x16[MROWS * DM];
__device__ __align__(16) __half g_wqkv16[3 * DM * DM];
__device__ __align__(16) __half g_wo16[DM * DM];
__device__ __align__(16) __half g_qkv16[MROWS * 3 * DM];
__device__ __align__(16) __half g_y16[MROWS * DM];

// ---------------------------------------------------------------------------
// PTX helpers (baseline PTX only: cp.async + ldmatrix + mma.sync)
// ---------------------------------------------------------------------------
__device__ __forceinline__ uint32_t smem_u32(const void* p) {
    uint32_t a;
    asm("{ .reg .u64 t; cvta.to.shared.u64 t, %1; cvt.u32.u64 %0, t; }"
        : "=r"(a) : "l"(p));
    return a;
}

__device__ __forceinline__ void cp_async16(uint32_t saddr, const void* gaddr) {
    asm volatile("cp.async.cg.shared.global [%0], [%1], 16;"
                 :: "r"(saddr), "l"(gaddr) : "memory");
}
#define CP_COMMIT() asm volatile("cp.async.commit_group;" ::: "memory")
#define CP_WAIT(n)  asm volatile("cp.async.wait_group %0;" :: "n"(n) : "memory")

__device__ __forceinline__ void ldm4(uint32_t* r, uint32_t addr) {
    asm volatile("ldmatrix.sync.aligned.m8n8.x4.shared.b16 {%0,%1,%2,%3}, [%4];"
                 : "=r"(r[0]), "=r"(r[1]), "=r"(r[2]), "=r"(r[3]) : "r"(addr));
}
__device__ __forceinline__ void ldm4t(uint32_t* r, uint32_t addr) {
    asm volatile("ldmatrix.sync.aligned.m8n8.x4.trans.shared.b16 {%0,%1,%2,%3}, [%4];"
                 : "=r"(r[0]), "=r"(r[1]), "=r"(r[2]), "=r"(r[3]) : "r"(addr));
}

__device__ __forceinline__ void mma_f16(float* d, const uint32_t* a,
                                        uint32_t b0, uint32_t b1) {
    asm volatile(
        "mma.sync.aligned.m16n8k16.row.col.f32.f16.f16.f32 "
        "{%0,%1,%2,%3}, {%4,%5,%6,%7}, {%8,%9}, {%0,%1,%2,%3};"
        : "+f"(d[0]), "+f"(d[1]), "+f"(d[2]), "+f"(d[3])
        : "r"(a[0]), "r"(a[1]), "r"(a[2]), "r"(a[3]), "r"(b0), "r"(b1));
}

// ---------------------------------------------------------------------------
// fp32 -> fp16 convert, 4 elems/thread
// ---------------------------------------------------------------------------
__global__ __launch_bounds__(256) void cvt_f16(
    const float* __restrict__ in, __half* __restrict__ out, int n4)
{
    int i = blockIdx.x * blockDim.x + threadIdx.x;
    if (i >= n4) return;
    float4 v = ((const float4*)in)[i];
    __half2 p0 = __floats2half2_rn(v.x, v.y);
    __half2 p1 = __floats2half2_rn(v.z, v.w);
    ((__half2*)out)[i * 2]     = p0;
    ((__half2*)out)[i * 2 + 1] = p1;
}

// ---------------------------------------------------------------------------
// C = A @ B^T + bias, 1-pass fp16 HMMA, fp32 accumulate.
// 256 threads, warp grid 4(M)x2(N), warp tile 32x64, CTA tile 128x128,
// BK=32, 3-stage cp.async pipeline, 2 CTAs/SM for cross-CTA overlap.
// OUTM=0: fp32 C.  OUTM=1: fp16 Ch.
// ---------------------------------------------------------------------------
#define STAGE_BYTES 16384          // A 8KB | B 8KB
#define GEMM_SMEM  (3 * STAGE_BYTES)

__device__ __forceinline__ uint32_t sw_off(int row, int c) {
    return (uint32_t)(row * 64 + ((c ^ ((row >> 1) & 3)) * 16));
}

template<int OUTM>
__global__ __launch_bounds__(256, 2) void gemm_f16(
    const __half* __restrict__ Ah, const __half* __restrict__ Bh,
    const float* __restrict__ bias,
    float* __restrict__ C, __half* __restrict__ Ch,
    int N, int K)
{
    extern __shared__ char smem[];
    const uint32_t sb = smem_u32(smem);
    const int tid = threadIdx.x;
    const int lane = tid & 31;
    const int wid = tid >> 5;           // 0..7
    const int warpM = wid & 3;          // M slice: warpM*32
    const int warpN = wid >> 2;         // N slice: warpN*64
    const int bm = blockIdx.y * 128;
    const int bn = blockIdx.x * 128;
    const int NC = K >> 5;

    const int g  = lane >> 3;
    const int l7 = lane & 7;
    const int arow = (g & 1) * 8 + l7;
    const int acg  = g >> 1;
    const int brow = (g >> 1) * 8 + l7;
    const int bcg  = g & 1;

    uint32_t aRow[2], aSw[2];
#pragma unroll
    for (int mt = 0; mt < 2; mt++) {
        int r = warpM * 32 + mt * 16 + arow;
        aRow[mt] = (uint32_t)(r * 64);
        aSw[mt] = (uint32_t)((r >> 1) & 3);
    }
    uint32_t bRow[4], bSw[4];
#pragma unroll
    for (int ng = 0; ng < 4; ng++) {
        int r = warpN * 64 + ng * 16 + brow;
        bRow[ng] = (uint32_t)(r * 64);
        bSw[ng] = (uint32_t)((r >> 1) & 3);
    }

    float acc[2][8][4];
#pragma unroll
    for (int mt = 0; mt < 2; mt++)
#pragma unroll
        for (int nt = 0; nt < 8; nt++)
#pragma unroll
            for (int e = 0; e < 4; e++) acc[mt][nt][e] = 0.f;

    const __half* srcA = Ah + (size_t)bm * K;
    const __half* srcB = Bh + (size_t)bn * K;

    auto load_stage = [&](int kc, int st) {
        const uint32_t stbase = sb + st * STAGE_BYTES;
#pragma unroll
        for (int q = 0; q < 4; q++) {
            int cid = tid + q * 256;          // 0..1023
            int sub = cid >> 9;               // 0:A 1:B
            int ci  = cid & 511;
            int row = ci >> 2;
            int c   = ci & 3;
            uint32_t saddr = stbase + sub * 8192 + sw_off(row, c);
            const __half* gp = (sub ? srcB : srcA)
                + (size_t)row * K + kc * 32 + c * 8;
            cp_async16(saddr, gp);
        }
        CP_COMMIT();
    };

    load_stage(0, 0);
    load_stage(1, 1);

    for (int i = 0; i < NC; i++) {
        if (i < NC - 1) { CP_WAIT(1); } else { CP_WAIT(0); }
        __syncthreads();

        const uint32_t stbase = sb + (i % 3) * STAGE_BYTES;
#pragma unroll
        for (int ks = 0; ks < 2; ks++) {
            uint32_t a[2][4], b[4][4];
#pragma unroll
            for (int mt = 0; mt < 2; mt++) {
                uint32_t slot = (uint32_t)((2 * ks + acg) ^ aSw[mt]) * 16;
                ldm4(a[mt], stbase + aRow[mt] + slot);
            }
#pragma unroll
            for (int ng = 0; ng < 4; ng++) {
                uint32_t slot = (uint32_t)((2 * ks + bcg) ^ bSw[ng]) * 16;
                ldm4(b[ng], stbase + 8192 + bRow[ng] + slot);
            }
#pragma unroll
            for (int mt = 0; mt < 2; mt++)
#pragma unroll
                for (int ng = 0; ng < 4; ng++) {
                    mma_f16(acc[mt][2 * ng],     a[mt], b[ng][0], b[ng][1]);
                    mma_f16(acc[mt][2 * ng + 1], a[mt], b[ng][2], b[ng][3]);
                }
        }

        // stage (i+2)%3 == (i-1)%3 was fully consumed before this iter's barrier
        if (i + 2 < NC) load_stage(i + 2, (i + 2) % 3);
    }

#pragma unroll
    for (int mt = 0; mt < 2; mt++) {
#pragma unroll
        for (int nt = 0; nt < 8; nt++) {
            int row0 = bm + warpM * 32 + mt * 16 + (lane >> 2);
            int col  = bn + warpN * 64 + nt * 8 + (lane & 3) * 2;
            float b0 = bias[col], b1 = bias[col + 1];
            float v0 = acc[mt][nt][0] + b0, v1 = acc[mt][nt][1] + b1;
            float v2 = acc[mt][nt][2] + b0, v3 = acc[mt][nt][3] + b1;
            if (OUTM == 0) {
                float2 p0 = { v0, v1 }, p1 = { v2, v3 };
                *(float2*)(C + (size_t)row0 * N + col) = p0;
                *(float2*)(C + (size_t)(row0 + 8) * N + col) = p1;
            } else {
                __half2 h0 = __floats2half2_rn(v0, v1);
                __half2 h1 = __floats2half2_rn(v2, v3);
                *(__half2*)(Ch + (size_t)row0 * N + col) = h0;
                *(__half2*)(Ch + (size_t)(row0 + 8) * N + col) = h1;
            }
        }
    }
}

// ---------------------------------------------------------------------------
// Causal flash attention, 1-pass fp16 HMMA (unchanged from R9).
// grid (16, B*NH); CTA: 128-query tile for one (b,h); 256 threads / 8 warps.
// ---------------------------------------------------------------------------
#define FSMEM (16384 + 2 * 16384)   // Q (16K) + 2 stages of K|V (16K each)

__global__ __launch_bounds__(256, 1) void flash_f16(
    const __half* __restrict__ qkv,
    const int* __restrict__ mask,
    __half* __restrict__ y)
{
    extern __shared__ char smem[];
    const uint32_t sb = smem_u32(smem);
    const int tid = threadIdx.x;
    const int lane = tid & 31, wid = tid >> 5;
    const int qt = 15 - (int)blockIdx.x;          // descending work order
    const int bh = blockIdx.y, b = bh >> 4, h = bh & 15;
    const int nkt = 2 * qt + 2;
    const int l7 = lane & 7, bit3 = (lane >> 3) & 1, bit4 = (lane >> 4) & 1;

    const uint32_t QB = sb, ST = sb + 16384;

    // Q load: 128 rows x 128B
    {
        const size_t rq = (size_t)(b * BN_T + qt * 128);
#pragma unroll
        for (int q = 0; q < 4; q++) {
            int cid = q * 256 + tid;
            int row = cid >> 3, c = cid & 7;
            const __half* gp = qkv + (rq + row) * 3072 + h * 64 + c * 8;
            cp_async16(QB + row * 128 + (((c ^ (row & 7))) << 4), gp);
        }
        CP_COMMIT();
    }

    auto load_kv = [&](int kt, int st) {
        const uint32_t base = ST + st * 16384;
        const size_t rk = (size_t)(b * BN_T + kt * 64);
#pragma unroll
        for (int q = 0; q < 4; q++) {
            int cid = q * 256 + tid;
            int sub = cid >> 9, ci = cid & 511, row = ci >> 3, c = ci & 7;
            int colb = sub ? (2048 + h * 64) : (1024 + h * 64);
            const __half* gp = qkv + (rk + row) * 3072 + colb + c * 8;
            cp_async16(base + sub * 8192 + row * 128 + (((c ^ (row & 7))) << 4), gp);
        }
        CP_COMMIT();
    };

    load_kv(0, 0);
    load_kv(1, 1);

    CP_WAIT(2);            // Q resident
    __syncthreads();

    // Q fragments (register-resident)
    uint32_t qf[4][4];
    {
        const uint32_t rb = (uint32_t)((wid * 16 + bit3 * 8 + l7) * 128);
#pragma unroll
        for (int ks = 0; ks < 4; ks++) {
            uint32_t sl = ((uint32_t)((ks * 2 + bit4) ^ l7)) << 4;
            ldm4(qf[ks], QB + rb + sl);
        }
    }

    float o[8][4];
#pragma unroll
    for (int nt = 0; nt < 8; nt++)
#pragma unroll
        for (int e = 0; e < 4; e++) o[nt][e] = 0.f;
    float m0 = -1e30f, m1 = -1e30f, l0 = 0.f, l1 = 0.f;

    const int row0 = qt * 128 + wid * 16 + (lane >> 2);
    const int col_in = (lane & 3) * 2;

    for (int kt = 0; kt < nkt; kt++) {
        if (kt + 1 < nkt) { CP_WAIT(1); } else { CP_WAIT(0); }
        __syncthreads();
        const uint32_t kb = ST + (kt & 1) * 16384;

        // ---- S = (Q Kᵀ) * 0.125 ----
        float s[8][4];
#pragma unroll
        for (int nt = 0; nt < 8; nt++)
#pragma unroll
            for (int e = 0; e < 4; e++) s[nt][e] = 0.f;

#pragma unroll
        for (int ks = 0; ks < 4; ks++) {
            uint32_t k4[4][4];
#pragma unroll
            for (int np = 0; np < 4; np++) {
                uint32_t rb = (uint32_t)((np * 16 + bit4 * 8 + l7) * 128);
                uint32_t sl = ((uint32_t)((ks * 2 + bit3) ^ l7)) << 4;
                ldm4(k4[np], kb + rb + sl);
            }
#pragma unroll
            for (int np = 0; np < 4; np++) {
                mma_f16(s[2*np],   qf[ks], k4[np][0], k4[np][1]);
                mma_f16(s[2*np+1], qf[ks], k4[np][2], k4[np][3]);
            }
        }

        const bool diag = (kt >= 2 * qt);
#pragma unroll
        for (int nt = 0; nt < 8; nt++) {
#pragma unroll
            for (int e = 0; e < 4; e++) s[nt][e] *= 0.125f;
            if (diag) {
                int key = kt * 64 + nt * 8 + col_in;
                if (key     > row0)     s[nt][0] = -1e30f;
                if (key + 1 > row0)     s[nt][1] = -1e30f;
                if (key     > row0 + 8) s[nt][2] = -1e30f;
                if (key + 1 > row0 + 8) s[nt][3] = -1e30f;
            }
        }

        // ---- online softmax ----
        float rm0 = s[0][0], rm1 = s[0][2];
#pragma unroll
        for (int nt = 0; nt < 8; nt++) {
            rm0 = fmaxf(rm0, fmaxf(s[nt][0], s[nt][1]));
            rm1 = fmaxf(rm1, fmaxf(s[nt][2], s[nt][3]));
        }
        rm0 = fmaxf(rm0, __shfl_xor_sync(~0u, rm0, 1));
        rm0 = fmaxf(rm0, __shfl_xor_sync(~0u, rm0, 2));
        rm1 = fmaxf(rm1, __shfl_xor_sync(~0u, rm1, 1));
        rm1 = fmaxf(rm1, __shfl_xor_sync(~0u, rm1, 2));
        float mn0 = fmaxf(m0, rm0), mn1 = fmaxf(m1, rm1);
        float c0 = __expf(m0 - mn0), c1 = __expf(m1 - mn1);
        float sum0 = 0.f, sum1 = 0.f;
#pragma unroll
        for (int nt = 0; nt < 8; nt++) {
            s[nt][0] = __expf(s[nt][0] - mn0);
            s[nt][1] = __expf(s[nt][1] - mn0);
            s[nt][2] = __expf(s[nt][2] - mn1);
            s[nt][3] = __expf(s[nt][3] - mn1);
            sum0 += s[nt][0] + s[nt][1];
            sum1 += s[nt][2] + s[nt][3];
        }
        sum0 += __shfl_xor_sync(~0u, sum0, 1);
        sum0 += __shfl_xor_sync(~0u, sum0, 2);
        sum1 += __shfl_xor_sync(~0u, sum1, 1);
        sum1 += __shfl_xor_sync(~0u, sum1, 2);
        l0 = l0 * c0 + sum0; l1 = l1 * c1 + sum1;
        m0 = mn0; m1 = mn1;
#pragma unroll
        for (int nt = 0; nt < 8; nt++) {
            o[nt][0] *= c0; o[nt][1] *= c0;
            o[nt][2] *= c1; o[nt][3] *= c1;
        }

        // ---- pack P into fp16 A-fragments ----
        uint32_t pa[4][4];
#pragma unroll
        for (int j = 0; j < 4; j++) {
#pragma unroll
            for (int e = 0; e < 4; e++) {
                int nt = 2 * j + (e >> 1);
                int li = (e & 1) * 2;
                __half2 hp = __floats2half2_rn(s[nt][li], s[nt][li + 1]);
                pa[j][e] = *(uint32_t*)&hp;
            }
        }

        // ---- O += P V (V via ldmatrix.trans) ----
#pragma unroll
        for (int j = 0; j < 4; j++) {
            uint32_t v4[4][4];
#pragma unroll
            for (int g = 0; g < 4; g++) {
                uint32_t rb = (uint32_t)((j * 16 + bit3 * 8 + l7) * 128);
                uint32_t sl = ((uint32_t)((g * 2 + bit4) ^ l7)) << 4;
                ldm4t(v4[g], kb + 8192 + rb + sl);
            }
#pragma unroll
            for (int g = 0; g < 4; g++) {
                mma_f16(o[2*g],   pa[j], v4[g][0], v4[g][1]);
                mma_f16(o[2*g+1], pa[j], v4[g][2], v4[g][3]);
            }
        }

        __syncthreads();
        if (kt + 2 < nkt) load_kv(kt + 2, kt & 1);
    }

    // ---- epilogue: normalize, query-mask, fp16 write ----
    const int gr0 = b * BN_T + row0;
    const float sc0 = (mask[gr0] ? 1.f : 0.f) / l0;
    const float sc1 = (mask[gr0 + 8] ? 1.f : 0.f) / l1;
#pragma unroll
    for (int nt = 0; nt < 8; nt++) {
        int col = h * 64 + nt * 8 + col_in;
        __half2 h0 = __floats2half2_rn(o[nt][0] * sc0, o[nt][1] * sc0);
        __half2 h1 = __floats2half2_rn(o[nt][2] * sc1, o[nt][3] * sc1);
        *(__half2*)(y + (size_t)gr0 * DM + col) = h0;
        *(__half2*)(y + (size_t)(gr0 + 8) * DM + col) = h1;
    }
}

// ---------------------------------------------------------------------------
extern "C" void kernel_launch(void* const* d_in, const int* in_sizes, int n_in,
                              void* d_out, int out_size)
{
    const float* x    = (const float*)d_in[0];
    const int*   mask = (const int*)  d_in[1];
    const float* Wqkv = (const float*)d_in[2];
    const float* bqkv = (const float*)d_in[3];
    const float* Wo   = (const float*)d_in[4];
    const float* bo   = (const float*)d_in[5];
    float* out = (float*)d_out;

    __half *x16, *wqkv16, *wo16, *qkv16, *y16;
    cudaGetSymbolAddress((void**)&x16,    g_x16);
    cudaGetSymbolAddress((void**)&wqkv16, g_wqkv16);
    cudaGetSymbolAddress((void**)&wo16,   g_wo16);
    cudaGetSymbolAddress((void**)&qkv16,  g_qkv16);
    cudaGetSymbolAddress((void**)&y16,    g_y16);

    cudaFuncSetAttribute(gemm_f16<0>,
                         cudaFuncAttributeMaxDynamicSharedMemorySize, GEMM_SMEM);
    cudaFuncSetAttribute(gemm_f16<1>,
                         cudaFuncAttributeMaxDynamicSharedMemorySize, GEMM_SMEM);
    cudaFuncSetAttribute(flash_f16,
                         cudaFuncAttributeMaxDynamicSharedMemorySize, FSMEM);

    cvt_f16<<<(MROWS * DM / 4 + 255) / 256, 256>>>(x, x16, MROWS * DM / 4);
    cvt_f16<<<(3 * DM * DM / 4 + 255) / 256, 256>>>(Wqkv, wqkv16, 3 * DM * DM / 4);
    cvt_f16<<<(DM * DM / 4 + 255) / 256, 256>>>(Wo, wo16, DM * DM / 4);

    // QKV projection -> fp16 qkv
    gemm_f16<1><<<dim3(3 * DM / 128, MROWS / 128), 256, GEMM_SMEM>>>(
        x16, wqkv16, bqkv, nullptr, qkv16, 3 * DM, DM);

    // Causal flash attention -> fp16 y
    flash_f16<<<dim3(16, 4 * NH), 256, FSMEM>>>(qkv16, mask, y16);

    // Output projection -> fp32 out
    gemm_f16<0><<<dim3(DM / 128, MROWS / 128), 256, GEMM_SMEM>>>(
        y16, wo16, bo, out, nullptr, DM, DM);
}